// round 17
// baseline (speedup 1.0000x reference)
#include <cuda_runtime.h>
#include <cuda_bf16.h>
#include <cuda_fp16.h>
#include <math.h>
#include <stdint.h>

#define NN   204800      // total nodes
#define DD   64          // embed dim
#define EE   3276800     // edges
#define NB   8192        // graphs
#define HID  1600        // 25 * 64
#define NBLK 200         // NN / 1024 scan blocks

// conv GEMM tiling
#define BM 128
#define BN 64
#define BK 32

// ---- tf32 conv kernel smem (dynamic) ----
#define ASTRIDE 44
#define BSTRIDE 72
#define A_BUF_F (BM * ASTRIDE)
#define B_BUF_F (BK * BSTRIDE)
#define SM_B_BASE (2 * A_BUF_F)
#define SM_TOTAL_B ((2 * A_BUF_F + 2 * B_BUF_F) * 4)

// ---- bf16 head GEMM: BM 128 x BN3 160 x BK 32, 256 threads, 3-stage ----
#define BM3   128
#define BN3   160
#define ASTR2 20                              // 16 data words + 4 pad
#define BSTR4 84                              // 80 data words + 4 pad (B raw rows)
#define A_WORDS_BUF (BM3 * ASTR2)             // 2560 words / stage
#define B_WORD_BASE (3 * A_WORDS_BUF)         // 7680
#define B_WORDS_BUF (BK * BSTR4)              // 2688 words / stage
#define SM3_BYTES ((B_WORD_BASE + 3 * B_WORDS_BUF) * 4)   // 62976

// ---------------- scratch (device globals; no allocation) ----------------
__device__ int   g_deg[NN];
__device__ float g_dinv[NN];
__device__ int   g_off[NN + 1];
__device__ int   g_cur[NN];
__device__ int   g_bsum[NBLK];
__device__ int   g_bscan[NBLK + 1];
__device__ int   g_csr[EE];
__device__ __half g_hs[(size_t)NN * DD];           // (x @ W_conv) * dinv[row], fp16
__device__ __nv_bfloat16 g_h2b[(size_t)NN * DD];   // relu(agg + bc) bf16
__device__ __nv_bfloat16 g_W1b[(size_t)HID * HID]; // W1 bf16
__device__ float g_logits[NB * 2];                 // fused classifier partials

// ---------------- degree ----------------
__global__ void k_deg_count(const int* __restrict__ dst) {
    int e4 = (blockIdx.x * blockDim.x + threadIdx.x) * 4;
    if (e4 >= EE) return;
    int4 d = *(const int4*)(dst + e4);
    atomicAdd(&g_deg[d.x], 1);
    atomicAdd(&g_deg[d.y], 1);
    atomicAdd(&g_deg[d.z], 1);
    atomicAdd(&g_deg[d.w], 1);
}

// ---------------- scan of g_deg -> g_off (+ dinv fused) ----------------
__global__ __launch_bounds__(1024)
void k_scan1() {
    __shared__ int sh[1024];
    int i = blockIdx.x * 1024 + threadIdx.x;
    int v = g_deg[i];
    g_dinv[i] = rsqrtf((float)(v + 1));
    sh[threadIdx.x] = v;
    __syncthreads();
#pragma unroll
    for (int off = 1; off < 1024; off <<= 1) {
        int t = (threadIdx.x >= off) ? sh[threadIdx.x - off] : 0;
        __syncthreads();
        sh[threadIdx.x] += t;
        __syncthreads();
    }
    g_off[i] = sh[threadIdx.x] - v;     // block-local exclusive
    g_cur[i] = 0;
    if (threadIdx.x == 1023) g_bsum[blockIdx.x] = sh[1023];
}
__global__ __launch_bounds__(256)
void k_scan2() {
    __shared__ int sh[256];
    int t = threadIdx.x;
    int v = (t < NBLK) ? g_bsum[t] : 0;
    sh[t] = v;
    __syncthreads();
#pragma unroll
    for (int off = 1; off < 256; off <<= 1) {
        int u = (t >= off) ? sh[t - off] : 0;
        __syncthreads();
        sh[t] += u;
        __syncthreads();
    }
    if (t < NBLK) g_bscan[t] = sh[t] - v;
    if (t == NBLK) g_bscan[NBLK] = 0;       // sentinel for node+1 == NN
    if (t == NBLK - 1) g_off[NN] = sh[t];   // == EE (final)
}

// ---------------- CSR fill (4 edges / thread; bscan folded in) --------------
__global__ void k_fill(const int* __restrict__ src, const int* __restrict__ dst) {
    int e4 = (blockIdx.x * blockDim.x + threadIdx.x) * 4;
    if (e4 >= EE) return;
    int4 d = *(const int4*)(dst + e4);
    int4 s = *(const int4*)(src + e4);
    g_csr[g_off[d.x] + g_bscan[d.x >> 10] + atomicAdd(&g_cur[d.x], 1)] = s.x;
    g_csr[g_off[d.y] + g_bscan[d.y >> 10] + atomicAdd(&g_cur[d.y], 1)] = s.y;
    g_csr[g_off[d.z] + g_bscan[d.z >> 10] + atomicAdd(&g_cur[d.z], 1)] = s.z;
    g_csr[g_off[d.w] + g_bscan[d.w >> 10] + atomicAdd(&g_cur[d.w], 1)] = s.w;
}

// ---------------- W1 -> bf16 ----------------
__global__ void k_cvt_w1(const float* __restrict__ W1) {
    size_t i4 = ((size_t)blockIdx.x * blockDim.x + threadIdx.x) * 4;
    if (i4 >= (size_t)HID * HID) return;
    float4 v = *(const float4*)(W1 + i4);
    uint2 o;
    o.x = ((uint32_t)__bfloat16_as_ushort(__float2bfloat16(v.x)))
        | ((uint32_t)__bfloat16_as_ushort(__float2bfloat16(v.y)) << 16);
    o.y = ((uint32_t)__bfloat16_as_ushort(__float2bfloat16(v.z)))
        | ((uint32_t)__bfloat16_as_ushort(__float2bfloat16(v.w)) << 16);
    *(uint2*)(g_W1b + i4) = o;
}

// ================= tf32 mma.sync GEMM (conv): hs = fp16((A @ B) * dinv[row]) ==
__device__ __forceinline__ uint32_t f2tf(float f) {
    uint32_t u;
    asm("cvt.rna.tf32.f32 %0, %1;" : "=r"(u) : "f"(f));
    return u;
}
__device__ __forceinline__ void mma_tf32(float* c, const uint32_t* a, const uint32_t* b) {
    asm volatile(
        "mma.sync.aligned.m16n8k8.row.col.f32.tf32.tf32.f32 "
        "{%0,%1,%2,%3}, {%4,%5,%6,%7}, {%8,%9}, {%0,%1,%2,%3};"
        : "+f"(c[0]), "+f"(c[1]), "+f"(c[2]), "+f"(c[3])
        : "r"(a[0]), "r"(a[1]), "r"(a[2]), "r"(a[3]), "r"(b[0]), "r"(b[1]));
}

template<int KTOT, int NTOT, int KIT>
__global__ __launch_bounds__(256, 2)
void k_gemm_conv(const float* __restrict__ A, const float* __restrict__ B,
                 __half* __restrict__ C, const float* __restrict__ dinv) {
    extern __shared__ float sm[];
#define AS_(b, r, c) sm[(b) * A_BUF_F + (r) * ASTRIDE + (c)]
#define BS_(b, k, n) sm[SM_B_BASE + (b) * B_BUF_F + (k) * BSTRIDE + (n)]

    const int tid = threadIdx.x;
    const int wid = tid >> 5;
    const int lid = tid & 31;
    const int g   = lid >> 2;
    const int tq  = lid & 3;
    const int wm  = wid >> 1;
    const int wn  = wid & 1;
    const int bm  = blockIdx.y * BM;
    const int bn  = blockIdx.x * BN;

    const float* Ag = A + (size_t)bm * KTOT;
    const float* Bg = B + bn;

    float acc[2][4][4];
#pragma unroll
    for (int mt = 0; mt < 2; mt++)
#pragma unroll
        for (int nt = 0; nt < 4; nt++)
#pragma unroll
            for (int j = 0; j < 4; j++) acc[mt][nt][j] = 0.f;

    const int a_row = tid >> 3;
    const int a_c4  = (tid & 7) * 4;
    const int b_row = tid >> 4;
    const int b_c4  = (tid & 15) * 4;

    float4 pa[4], pb[2];
#pragma unroll
    for (int i = 0; i < 4; i++)
        pa[i] = *(const float4*)(Ag + (size_t)(a_row + i * 32) * KTOT + a_c4);
#pragma unroll
    for (int i = 0; i < 2; i++)
        pb[i] = *(const float4*)(Bg + (size_t)(b_row + i * 16) * NTOT + b_c4);
#pragma unroll
    for (int i = 0; i < 4; i++) {
        uint4 t = make_uint4(f2tf(pa[i].x), f2tf(pa[i].y), f2tf(pa[i].z), f2tf(pa[i].w));
        *(uint4*)&AS_(0, a_row + i * 32, a_c4) = t;
    }
#pragma unroll
    for (int i = 0; i < 2; i++) {
        uint4 t = make_uint4(f2tf(pb[i].x), f2tf(pb[i].y), f2tf(pb[i].z), f2tf(pb[i].w));
        *(uint4*)&BS_(0, b_row + i * 16, b_c4) = t;
    }
    __syncthreads();

    for (int k0 = 0; k0 < KIT; k0++) {
        const int b = k0 & 1;
        if (k0 + 1 < KIT) {
            const float* An = Ag + (k0 + 1) * BK;
            const float* Bn = Bg + (size_t)(k0 + 1) * BK * NTOT;
#pragma unroll
            for (int i = 0; i < 4; i++)
                pa[i] = *(const float4*)(An + (size_t)(a_row + i * 32) * KTOT + a_c4);
#pragma unroll
            for (int i = 0; i < 2; i++)
                pb[i] = *(const float4*)(Bn + (size_t)(b_row + i * 16) * NTOT + b_c4);
        }
#pragma unroll
        for (int ks = 0; ks < 4; ks++) {
            const int kb = ks * 8;
            uint32_t af[2][4], bf[4][2];
#pragma unroll
            for (int mt = 0; mt < 2; mt++) {
                const int r = wm * 32 + mt * 16 + g;
                af[mt][0] = __float_as_uint(AS_(b, r,     kb + tq));
                af[mt][1] = __float_as_uint(AS_(b, r + 8, kb + tq));
                af[mt][2] = __float_as_uint(AS_(b, r,     kb + tq + 4));
                af[mt][3] = __float_as_uint(AS_(b, r + 8, kb + tq + 4));
            }
#pragma unroll
            for (int nt = 0; nt < 4; nt++) {
                const int n = wn * 32 + nt * 8 + g;
                bf[nt][0] = __float_as_uint(BS_(b, kb + tq,     n));
                bf[nt][1] = __float_as_uint(BS_(b, kb + tq + 4, n));
            }
#pragma unroll
            for (int mt = 0; mt < 2; mt++)
#pragma unroll
                for (int nt = 0; nt < 4; nt++)
                    mma_tf32(acc[mt][nt], af[mt], bf[nt]);
        }
        if (k0 + 1 < KIT) {
            const int nb = b ^ 1;
#pragma unroll
            for (int i = 0; i < 4; i++) {
                uint4 t = make_uint4(f2tf(pa[i].x), f2tf(pa[i].y), f2tf(pa[i].z), f2tf(pa[i].w));
                *(uint4*)&AS_(nb, a_row + i * 32, a_c4) = t;
            }
#pragma unroll
            for (int i = 0; i < 2; i++) {
                uint4 t = make_uint4(f2tf(pb[i].x), f2tf(pb[i].y), f2tf(pb[i].z), f2tf(pb[i].w));
                *(uint4*)&BS_(nb, b_row + i * 16, b_c4) = t;
            }
        }
        __syncthreads();
    }

#pragma unroll
    for (int mt = 0; mt < 2; mt++) {
        const int r0 = bm + wm * 32 + mt * 16 + g;
        const float d0 = dinv[r0];
        const float d1 = dinv[r0 + 8];
#pragma unroll
        for (int nt = 0; nt < 4; nt++) {
            const int cb = bn + wn * 32 + nt * 8 + tq * 2;
            __half2 h0 = __floats2half2_rn(acc[mt][nt][0] * d0, acc[mt][nt][1] * d0);
            *(__half2*)(C + (size_t)r0 * NTOT + cb) = h0;
            __half2 h1 = __floats2half2_rn(acc[mt][nt][2] * d1, acc[mt][nt][3] * d1);
            *(__half2*)(C + (size_t)(r0 + 8) * NTOT + cb) = h1;
        }
    }
#undef AS_
#undef BS_
}

// ------- CSR aggregate: half-warp per edge (uint2 gather, fp32 acc) ---------
__device__ __forceinline__ void acc_add(float4& a, uint2 v) {
    float2 f0 = __half22float2(*(__half2*)&v.x);
    float2 f1 = __half22float2(*(__half2*)&v.y);
    a.x += f0.x; a.y += f0.y; a.z += f1.x; a.w += f1.y;
}

__global__ __launch_bounds__(256)
void k_aggregate(const float* __restrict__ bc, int blk_base) {
    const int node = (blockIdx.x + blk_base) * 8 + (threadIdx.x >> 5);
    const int lane = threadIdx.x & 31;
    const int half = lane >> 4;
    const int l16  = lane & 15;

    const uint2* hs4 = (const uint2*)g_hs;
    float4 acc = make_float4(0.f, 0.f, 0.f, 0.f);

    if (half == 0)
        acc_add(acc, hs4[(size_t)node * 16 + l16]);

    const int beg = g_off[node]     + g_bscan[node >> 10];
    const int end = g_off[node + 1] + g_bscan[(node + 1) >> 10];

    int i = beg + half;
    for (; i + 6 < end; i += 8) {
        int s0 = g_csr[i];
        int s1 = g_csr[i + 2];
        int s2 = g_csr[i + 4];
        int s3 = g_csr[i + 6];
        uint2 v0 = hs4[(size_t)s0 * 16 + l16];
        uint2 v1 = hs4[(size_t)s1 * 16 + l16];
        uint2 v2 = hs4[(size_t)s2 * 16 + l16];
        uint2 v3 = hs4[(size_t)s3 * 16 + l16];
        acc_add(acc, v0); acc_add(acc, v1);
        acc_add(acc, v2); acc_add(acc, v3);
    }
    for (; i < end; i += 2)
        acc_add(acc, hs4[(size_t)g_csr[i] * 16 + l16]);

    __syncwarp();
    acc.x += __shfl_xor_sync(0xffffffffu, acc.x, 16);
    acc.y += __shfl_xor_sync(0xffffffffu, acc.y, 16);
    acc.z += __shfl_xor_sync(0xffffffffu, acc.z, 16);
    acc.w += __shfl_xor_sync(0xffffffffu, acc.w, 16);

    if (half == 0) {
        const float sc = g_dinv[node];
        const int c = l16 * 4;
        float r0 = fmaxf(acc.x * sc + bc[c],     0.f);
        float r1 = fmaxf(acc.y * sc + bc[c + 1], 0.f);
        float r2 = fmaxf(acc.z * sc + bc[c + 2], 0.f);
        float r3 = fmaxf(acc.w * sc + bc[c + 3], 0.f);
        uint2 o;
        o.x = ((uint32_t)__bfloat16_as_ushort(__float2bfloat16(r0)))
            | ((uint32_t)__bfloat16_as_ushort(__float2bfloat16(r1)) << 16);
        o.y = ((uint32_t)__bfloat16_as_ushort(__float2bfloat16(r2)))
            | ((uint32_t)__bfloat16_as_ushort(__float2bfloat16(r3)) << 16);
        *(uint2*)(g_h2b + (size_t)node * DD + c) = o;
    }
}

// ===== bf16 mma.sync GEMM (head) + fused classifier partial-dot epilogue ====
__device__ __forceinline__ void mma_bf16(float* c, const uint32_t* a, const uint32_t* b) {
    asm volatile(
        "mma.sync.aligned.m16n8k16.row.col.f32.bf16.bf16.f32 "
        "{%0,%1,%2,%3}, {%4,%5,%6,%7}, {%8,%9}, {%0,%1,%2,%3};"
        : "+f"(c[0]), "+f"(c[1]), "+f"(c[2]), "+f"(c[3])
        : "r"(a[0]), "r"(a[1]), "r"(a[2]), "r"(a[3]), "r"(b[0]), "r"(b[1]));
}
__device__ __forceinline__ void ldsm_x4(uint32_t& r0, uint32_t& r1, uint32_t& r2,
                                        uint32_t& r3, uint32_t addr) {
    asm volatile("ldmatrix.sync.aligned.m8n8.x4.shared.b16 {%0,%1,%2,%3}, [%4];"
                 : "=r"(r0), "=r"(r1), "=r"(r2), "=r"(r3) : "r"(addr));
}
__device__ __forceinline__ void ldsm_x4t(uint32_t& r0, uint32_t& r1, uint32_t& r2,
                                         uint32_t& r3, uint32_t addr) {
    asm volatile("ldmatrix.sync.aligned.m8n8.x4.trans.shared.b16 {%0,%1,%2,%3}, [%4];"
                 : "=r"(r0), "=r"(r1), "=r"(r2), "=r"(r3) : "r"(addr));
}
__device__ __forceinline__ void ldsm_x2t(uint32_t& r0, uint32_t& r1, uint32_t addr) {
    asm volatile("ldmatrix.sync.aligned.m8n8.x2.trans.shared.b16 {%0,%1}, [%2];"
                 : "=r"(r0), "=r"(r1) : "r"(addr));
}
__device__ __forceinline__ void cp16(uint32_t dst, const void* src) {
    asm volatile("cp.async.ca.shared.global [%0], [%1], 16;" :: "r"(dst), "l"(src));
}

#define KIT2 (HID / BK)     // 50
__global__ __launch_bounds__(256, 2)
void k_gemm_bf16(const __nv_bfloat16* __restrict__ A, const __nv_bfloat16* __restrict__ B,
                 float* __restrict__ logits, const float* __restrict__ bias,
                 const float* __restrict__ W2, int bm_base) {
    extern __shared__ uint32_t smw[];

    const int tid = threadIdx.x;
    const int wid = tid >> 5;
    const int lid = tid & 31;
    const int tq  = lid & 3;
    const int g   = lid >> 2;
    const int wm  = wid >> 2;       // 0..1, 64 rows each
    const int wn  = wid & 3;        // 0..3, 40 cols each
    const int bm  = (blockIdx.y + bm_base) * BM3;
    const int bn  = blockIdx.x * BN3;

    const __nv_bfloat16* Ag = A + (size_t)bm * HID;
    const __nv_bfloat16* Bg = B + bn;

    float acc[4][5][4];
#pragma unroll
    for (int mt = 0; mt < 4; mt++)
#pragma unroll
        for (int nt = 0; nt < 5; nt++)
#pragma unroll
            for (int j = 0; j < 4; j++) acc[mt][nt][j] = 0.f;

    const uint32_t smbase = (uint32_t)__cvta_generic_to_shared(smw);
    const uint32_t ldsA_base = smbase
        + (uint32_t)((((wm * 64 + (lid & 15)) * ASTR2) + (lid >> 4) * 4) * 4);
    const int brow_off = ((lid >> 3) & 1) * 8 + (lid & 7);     // 0..15
    const int bcol_w   = wn * 20 + (lid >> 4) * 4;
    const int brow2    = lid & 15;
    const int bcol2_w  = wn * 20 + 16;

#define ISSUE_STAGE(s)                                                          \
    do {                                                                        \
        const int _buf = (s) % 3;                                               \
        const __nv_bfloat16* _As = Ag + (size_t)(s) * BK;                       \
        _Pragma("unroll")                                                       \
        for (int _i = 0; _i < 2; _i++) {                                        \
            int _c = tid + _i * 256;                                            \
            int _r = _c >> 2, _c4 = _c & 3;                                     \
            cp16(smbase + (uint32_t)((_buf * A_WORDS_BUF                        \
                    + _r * ASTR2 + _c4 * 4) * 4),                               \
                 _As + (size_t)_r * HID + _c4 * 8);                             \
        }                                                                       \
        const __nv_bfloat16* _Bs = Bg + (size_t)(s) * BK * HID;                 \
        _Pragma("unroll")                                                       \
        for (int _i = 0; _i < 2; _i++) {                                        \
            int _c = tid + _i * 256;                                            \
            int _r = _c / 20, _cc = _c % 20;                                    \
            cp16(smbase + (uint32_t)((B_WORD_BASE + _buf * B_WORDS_BUF          \
                    + _r * BSTR4 + _cc * 4) * 4),                               \
                 _Bs + (size_t)_r * HID + _cc * 8);                             \
        }                                                                       \
        if (tid < 128) {                                                        \
            int _c = tid + 512;                                                 \
            int _r = _c / 20, _cc = _c % 20;                                    \
            cp16(smbase + (uint32_t)((B_WORD_BASE + _buf * B_WORDS_BUF          \
                    + _r * BSTR4 + _cc * 4) * 4),                               \
                 _Bs + (size_t)_r * HID + _cc * 8);                             \
        }                                                                       \
        asm volatile("cp.async.commit_group;");                                 \
    } while (0)

    ISSUE_STAGE(0);
    ISSUE_STAGE(1);
    asm volatile("cp.async.wait_group 1;");
    __syncthreads();

    for (int k0 = 0; k0 < KIT2; k0++) {
        const int buf = k0 % 3;
        if (k0 + 2 < KIT2) ISSUE_STAGE(k0 + 2);

        const uint32_t bufA = ldsA_base + (uint32_t)(buf * A_WORDS_BUF * 4);
        const uint32_t bufB = smbase
            + (uint32_t)((B_WORD_BASE + buf * B_WORDS_BUF) * 4);
#pragma unroll
        for (int ks = 0; ks < 2; ks++) {
            const int kw = ks * 8;
            uint32_t af[4][4], bf[5][2];
#pragma unroll
            for (int mt = 0; mt < 4; mt++)
                ldsm_x4(af[mt][0], af[mt][1], af[mt][2], af[mt][3],
                        bufA + (uint32_t)((mt * 16 * ASTR2 + kw) * 4));
#pragma unroll
            for (int j = 0; j < 2; j++)
                ldsm_x4t(bf[2 * j][0], bf[2 * j][1], bf[2 * j + 1][0], bf[2 * j + 1][1],
                         bufB + (uint32_t)(((ks * 16 + brow_off) * BSTR4
                                            + bcol_w + j * 8) * 4));
            ldsm_x2t(bf[4][0], bf[4][1],
                     bufB + (uint32_t)(((ks * 16 + brow2) * BSTR4 + bcol2_w) * 4));
#pragma unroll
            for (int mt = 0; mt < 4; mt++)
#pragma unroll
                for (int nt = 0; nt < 5; nt++)
                    mma_bf16(acc[mt][nt], af[mt], bf[nt]);
        }

        if (k0 + 2 < KIT2) {
            asm volatile("cp.async.wait_group 1;");
        } else {
            asm volatile("cp.async.wait_group 0;");
        }
        __syncthreads();
    }
#undef ISSUE_STAGE

    // ---- fused classifier epilogue: partial logits, no o1 store ----
    float lg[4][2][2];
#pragma unroll
    for (int mt = 0; mt < 4; mt++)
#pragma unroll
        for (int h = 0; h < 2; h++) { lg[mt][h][0] = 0.f; lg[mt][h][1] = 0.f; }

#pragma unroll
    for (int nt = 0; nt < 5; nt++) {
        const int cb = bn + wn * 40 + nt * 8 + tq * 2;
        const float b0  = bias[cb],        b1  = bias[cb + 1];
        const float w00 = W2[cb * 2],      w01 = W2[cb * 2 + 1];
        const float w10 = W2[cb * 2 + 2],  w11 = W2[cb * 2 + 3];
#pragma unroll
        for (int mt = 0; mt < 4; mt++) {
            float v0 = fmaxf(acc[mt][nt][0] + b0, 0.f);
            float v1 = fmaxf(acc[mt][nt][1] + b1, 0.f);
            lg[mt][0][0] = fmaf(v0, w00, fmaf(v1, w10, lg[mt][0][0]));
            lg[mt][0][1] = fmaf(v0, w01, fmaf(v1, w11, lg[mt][0][1]));
            float v2 = fmaxf(acc[mt][nt][2] + b0, 0.f);
            float v3 = fmaxf(acc[mt][nt][3] + b1, 0.f);
            lg[mt][1][0] = fmaf(v2, w00, fmaf(v3, w10, lg[mt][1][0]));
            lg[mt][1][1] = fmaf(v2, w01, fmaf(v3, w11, lg[mt][1][1]));
        }
    }
#pragma unroll
    for (int mt = 0; mt < 4; mt++)
#pragma unroll
        for (int h = 0; h < 2; h++)
#pragma unroll
            for (int c = 0; c < 2; c++) {
                float v = lg[mt][h][c];
                v += __shfl_xor_sync(0xffffffffu, v, 1);
                v += __shfl_xor_sync(0xffffffffu, v, 2);
                lg[mt][h][c] = v;
            }
    if (tq == 0) {
#pragma unroll
        for (int mt = 0; mt < 4; mt++) {
            const int r0 = bm + wm * 64 + mt * 16 + g;
            atomicAdd(&logits[r0 * 2 + 0],       lg[mt][0][0]);
            atomicAdd(&logits[r0 * 2 + 1],       lg[mt][0][1]);
            atomicAdd(&logits[(r0 + 8) * 2 + 0], lg[mt][1][0]);
            atomicAdd(&logits[(r0 + 8) * 2 + 1], lg[mt][1][1]);
        }
    }
}

// ---------------- softmax over fused logits ----------------
__global__ void k_softmax(const float* __restrict__ b2, float* __restrict__ out) {
    int i = blockIdx.x * blockDim.x + threadIdx.x;
    if (i >= NB) return;
    float l0 = g_logits[i * 2 + 0] + b2[0];
    float l1 = g_logits[i * 2 + 1] + b2[1];
    float m  = fmaxf(l0, l1);
    float e0 = expf(l0 - m);
    float e1 = expf(l1 - m);
    float inv = 1.f / (e0 + e1);
    out[i * 2 + 0] = e0 * inv;
    out[i * 2 + 1] = e1 * inv;
}

// ---------------- launch ----------------
extern "C" void kernel_launch(void* const* d_in, const int* in_sizes, int n_in,
                              void* d_out, int out_size) {
    const float* x  = (const float*)d_in[0];
    const int*   ei = (const int*)  d_in[1];
    const float* Wc = (const float*)d_in[3];
    const float* bc = (const float*)d_in[4];
    const float* W1 = (const float*)d_in[5];
    const float* b1 = (const float*)d_in[6];
    const float* W2 = (const float*)d_in[7];
    const float* b2 = (const float*)d_in[8];
    float* out = (float*)d_out;

    float *pdinv, *plog;
    int* pdeg;
    __half* phs;
    __nv_bfloat16 *ph2b, *pW1b;
    cudaGetSymbolAddress((void**)&pdeg, g_deg);
    cudaGetSymbolAddress((void**)&phs,  g_hs);
    cudaGetSymbolAddress((void**)&pdinv, g_dinv);
    cudaGetSymbolAddress((void**)&ph2b, g_h2b);
    cudaGetSymbolAddress((void**)&pW1b, g_W1b);
    cudaGetSymbolAddress((void**)&plog, g_logits);

    static cudaStream_t s2 = nullptr;
    static cudaEvent_t ev_root = nullptr, ev_dinv = nullptr, ev_conv = nullptr;
    static cudaEvent_t ev_agg1 = nullptr, ev_g1 = nullptr;
    static int init_done = 0;
    if (!init_done) {
        cudaFuncSetAttribute(k_gemm_conv<DD, DD, DD / BK>,
                             cudaFuncAttributeMaxDynamicSharedMemorySize, SM_TOTAL_B);
        cudaFuncSetAttribute(k_gemm_bf16,
                             cudaFuncAttributeMaxDynamicSharedMemorySize, SM3_BYTES);
        cudaStreamCreateWithFlags(&s2, cudaStreamNonBlocking);
        cudaEventCreateWithFlags(&ev_root, cudaEventDisableTiming);
        cudaEventCreateWithFlags(&ev_dinv, cudaEventDisableTiming);
        cudaEventCreateWithFlags(&ev_conv, cudaEventDisableTiming);
        cudaEventCreateWithFlags(&ev_agg1, cudaEventDisableTiming);
        cudaEventCreateWithFlags(&ev_g1,   cudaEventDisableTiming);
        init_done = 1;
    }

    const int* src = ei;        // edge_index[0]
    const int* dst = ei + EE;   // edge_index[1]

    // ---- stream 0: degree / CSR chain ----
    cudaMemsetAsync(pdeg, 0, NN * sizeof(int), 0);
    cudaMemsetAsync(plog, 0, NB * 2 * sizeof(float), 0);
    cudaEventRecord(ev_root, 0);              // fork point for s2

    // s2: W1 conversion (independent) overlaps deg_count
    cudaStreamWaitEvent(s2, ev_root, 0);
    k_cvt_w1<<<((size_t)HID * HID / 4 + 255) / 256, 256, 0, s2>>>(W1);

    k_deg_count<<<(EE / 4 + 255) / 256, 256>>>(dst);
    k_scan1    <<<NBLK, 1024>>>();
    cudaEventRecord(ev_dinv, 0);              // dinv ready

    // s2: conv GEMM (needs dinv) overlaps scan2/fill
    cudaStreamWaitEvent(s2, ev_dinv, 0);
    {
        dim3 grid(DD / BN, NN / BM);
        k_gemm_conv<DD, DD, DD / BK>
            <<<grid, 256, SM_TOTAL_B, s2>>>(x, Wc, phs, pdinv);
    }
    cudaEventRecord(ev_conv, s2);

    k_scan2<<<1, 256>>>();
    k_fill <<<(EE / 4 + 255) / 256, 256>>>(src, dst);

    // join: aggregate needs CSR (stream 0) + hs (s2)
    cudaStreamWaitEvent(0, ev_conv, 0);

    // ---- pipelined aggregate / head-GEMM halves ----
    const int AGG_BLKS = NN / 8;              // 25600 total
    // half 1: nodes [0, NN/2)
    k_aggregate<<<AGG_BLKS / 2, 256>>>(bc, 0);
    cudaEventRecord(ev_agg1, 0);

    // s2: head GEMM for graphs [0, NB/2) overlaps aggregate half 2
    cudaStreamWaitEvent(s2, ev_agg1, 0);
    {
        dim3 grid(HID / BN3, NB / BM3 / 2);
        k_gemm_bf16<<<grid, 256, SM3_BYTES, s2>>>(ph2b, pW1b, plog, b1, W2, 0);
    }
    cudaEventRecord(ev_g1, s2);

    // stream0: aggregate half 2, then head GEMM for graphs [NB/2, NB)
    k_aggregate<<<AGG_BLKS / 2, 256>>>(bc, AGG_BLKS / 2);
    {
        dim3 grid(HID / BN3, NB / BM3 / 2);
        k_gemm_bf16<<<grid, 256, SM3_BYTES>>>(ph2b, pW1b, plog, b1, W2, NB / BM3 / 2);
    }

    // join both GEMM halves, then softmax
    cudaStreamWaitEvent(0, ev_g1, 0);
    k_softmax<<<(NB + 255) / 256, 256>>>(b2, out);
}